// round 3
// baseline (speedup 1.0000x reference)
#include <cuda_runtime.h>

#define BB 8
#define DD 16
#define HH 384
#define WW 384
#define HW (HH * WW)        /* 147456 */
#define NBV (DD * HW)       /* 2359296 per-batch voxels */
#define NT (BB * NBV)       /* 18874368 total voxels */

// Scratch (static device globals — no runtime allocation)
__device__ int g_parent[NT];
__device__ int g_aux[NT];            // strong-flag per root (CCL pass 1)
__device__ int g_cnt[NT];            // component size per root (CCL pass 2)
__device__ unsigned char g_mask[NT]; // bit0 = weak, bit1 = strong
__device__ unsigned char g_mask2[NT];// closed mask (0/1)

__device__ __forceinline__ int findRoot(const int* __restrict__ P, int i) {
    int p = P[i];
    while (p != i) { i = p; p = P[i]; }
    return i;
}

__device__ __forceinline__ void unite(int* P, int a, int b) {
    for (;;) {
        a = findRoot(P, a);
        b = findRoot(P, b);
        if (a == b) return;
        if (a > b) { int t = a; a = b; b = t; }
        int old = atomicMin(&P[b], a);
        if (old == b) return;
        b = old;    // someone else linked b; retry from its new parent
    }
}

// K1: thresholds + init parent + clear strong flags (float4 streaming)
__global__ void k_threshold(const float* __restrict__ in) {
    int i4 = blockIdx.x * blockDim.x + threadIdx.x;
    if (i4 >= NT / 4) return;
    float4 v = reinterpret_cast<const float4*>(in)[i4];
    int i = i4 * 4;
    uchar4 m;
    m.x = (unsigned char)((v.x >= 0.8f ? 1 : 0) | (v.x >= 0.92f ? 2 : 0));
    m.y = (unsigned char)((v.y >= 0.8f ? 1 : 0) | (v.y >= 0.92f ? 2 : 0));
    m.z = (unsigned char)((v.z >= 0.8f ? 1 : 0) | (v.z >= 0.92f ? 2 : 0));
    m.w = (unsigned char)((v.w >= 0.8f ? 1 : 0) | (v.w >= 0.92f ? 2 : 0));
    reinterpret_cast<uchar4*>(g_mask)[i4] = m;
    reinterpret_cast<int4*>(g_parent)[i4] = make_int4(i, i + 1, i + 2, i + 3);
    reinterpret_cast<int4*>(g_aux)[i4]    = make_int4(0, 0, 0, 0);
}

// K2/K5: union with -w, -h, -d neighbors (6-connectivity, within batch).
// Mask selected via template INSIDE device code (device symbols must not be
// passed as args from host).
template <bool SECOND>
__global__ void k_merge() {
    int i = blockIdx.x * blockDim.x + threadIdx.x;
    if (i >= NT) return;
    const unsigned char* mask = SECOND ? g_mask2 : g_mask;
    if (!(mask[i] & 1)) return;
    int w = i % WW;
    int h = (i / WW) % HH;
    int d = (i / HW) % DD;
    if (w > 0 && (mask[i - 1]  & 1)) unite(g_parent, i, i - 1);
    if (h > 0 && (mask[i - WW] & 1)) unite(g_parent, i, i - WW);
    if (d > 0 && (mask[i - HW] & 1)) unite(g_parent, i, i - HW);
}

// K3: path-compress + mark roots of components containing a strong voxel
__global__ void k_flatten_strong() {
    int i = blockIdx.x * blockDim.x + threadIdx.x;
    if (i >= NT) return;
    int r = findRoot(g_parent, i);
    g_parent[i] = r;
    if (g_mask[i] & 2) g_aux[r] = 1;   // idempotent store
}

// K4: apply hysteresis (weak & flagged root), then z-closing (radius 1) in a
// 16-bit column register; re-init parent and size counters for CCL pass 2.
__global__ void k_hyst_close() {
    int idx = blockIdx.x * blockDim.x + threadIdx.x;
    if (idx >= BB * HW) return;
    int b    = idx / HW;
    int rem  = idx - b * HW;
    int base = b * NBV + rem;

    unsigned colm = 0;
#pragma unroll
    for (int z = 0; z < DD; z++) {
        int i = base + z * HW;
        unsigned char mv = g_mask[i];
        if ((mv & 1) && g_aux[g_parent[i]]) colm |= (1u << z);
    }
    // dilate along z (OOB = 0), then erode along z (OOB = 1)
    unsigned dil = colm | (colm << 1) | (colm >> 1);
    unsigned ero = dil & ((dil << 1) | 1u) & ((dil >> 1) | 0x8000u);
#pragma unroll
    for (int z = 0; z < DD; z++) {
        int i = base + z * HW;
        g_mask2[i]  = (unsigned char)((ero >> z) & 1u);
        g_parent[i] = i;
        g_cnt[i]    = 0;
    }
}

// K6: path-compress + accumulate component sizes at roots
__global__ void k_flatten_count() {
    int i = blockIdx.x * blockDim.x + threadIdx.x;
    if (i >= NT) return;
    int r = findRoot(g_parent, i);
    g_parent[i] = r;
    if (g_mask2[i]) atomicAdd(&g_cnt[r], 1);
}

// K7: keep components of size >= 20, write fp32 0/1 (vectorized)
__global__ void k_final(float* __restrict__ out) {
    int i4 = blockIdx.x * blockDim.x + threadIdx.x;
    if (i4 >= NT / 4) return;
    int i = i4 * 4;
    uchar4 m = reinterpret_cast<const uchar4*>(g_mask2)[i4];
    float4 r;
    r.x = (m.x && g_cnt[g_parent[i    ]] >= 20) ? 1.0f : 0.0f;
    r.y = (m.y && g_cnt[g_parent[i + 1]] >= 20) ? 1.0f : 0.0f;
    r.z = (m.z && g_cnt[g_parent[i + 2]] >= 20) ? 1.0f : 0.0f;
    r.w = (m.w && g_cnt[g_parent[i + 3]] >= 20) ? 1.0f : 0.0f;
    reinterpret_cast<float4*>(out)[i4] = r;
}

extern "C" void kernel_launch(void* const* d_in, const int* in_sizes, int n_in,
                              void* d_out, int out_size) {
    const float* in = (const float*)d_in[0];
    float* out = (float*)d_out;

    const int TPB      = 256;
    const int GRID     = (NT + TPB - 1) / TPB;           // per-voxel kernels
    const int GRID4    = (NT / 4 + TPB - 1) / TPB;       // float4 kernels
    const int GRID_COL = (BB * HW + TPB - 1) / TPB;      // column kernel

    k_threshold<<<GRID4, TPB>>>(in);
    k_merge<false><<<GRID, TPB>>>();
    k_flatten_strong<<<GRID, TPB>>>();
    k_hyst_close<<<GRID_COL, TPB>>>();
    k_merge<true><<<GRID, TPB>>>();
    k_flatten_count<<<GRID, TPB>>>();
    k_final<<<GRID4, TPB>>>(out);
}

// round 4
// speedup vs baseline: 1.0957x; 1.0957x over previous
#include <cuda_runtime.h>

#define BB 8
#define DD 16
#define HH 384
#define WW 384
#define HW (HH * WW)            /* 147456 */
#define NBV (DD * HW)           /* 2359296 */
#define NT (BB * NBV)           /* 18874368 voxels */
#define NW (NT / 32)            /* 589824 bit-words */
#define ROWS (BB * DD * HH)     /* 49152 rows of W=384 = 12 words */
#define WPR 12                  /* words per row */

// ---- scratch (__device__ globals; no runtime allocation) ----
__device__ int g_parent[NT];
__device__ int g_cnt[NT];
__device__ unsigned g_weak[NW];
__device__ unsigned g_strong[NW];
__device__ unsigned g_auxb[NW];    // strong-flag bit per root voxel id
__device__ unsigned g_hyst[NW];    // hysteresis-kept mask bits
__device__ unsigned g_mask2[NW];   // closed mask bits

// ---- union-find ----
__device__ __forceinline__ int findRoot(const int* __restrict__ P, int i) {
    int p = P[i];
    while (p != i) { i = p; p = P[i]; }
    return i;
}
__device__ __forceinline__ void unite(int* P, int a, int b) {
    for (;;) {
        a = findRoot(P, a);
        b = findRoot(P, b);
        if (a == b) return;
        if (a > b) { int t = a; a = b; b = t; }
        int old = atomicMin(&P[b], a);
        if (old == b) return;
        b = old;
    }
}

// distance from bit (wd,lane) back to start of its run, given full-row bits rw[]
__device__ __forceinline__ int runBack(const unsigned* rw, int wd, int lane) {
    int c = 0;
    if (lane) c = __clz(~(rw[wd] << (32 - lane)));   // consecutive ones just below
    if (c == lane) {
        int k = wd - 1;
        while (k >= 0 && rw[k] == 0xffffffffu) { c += 32; k--; }
        if (k >= 0) c += __clz(~rw[k]);
    }
    return c;
}

// K1: threshold (ballot) -> bit masks; parent[p] = run start; clear aux bits
__global__ void k1_threshold(const float* __restrict__ in) {
    int t = blockIdx.x * blockDim.x + threadIdx.x;
    int warp = t >> 5, lane = t & 31;
    if (warp >= ROWS) return;
    int base = warp * WW;
    int wb = warp * WPR;
    unsigned rw[WPR];
    unsigned myW = 0, myS = 0;
#pragma unroll
    for (int wd = 0; wd < WPR; wd++) {
        float v = in[base + wd * 32 + lane];
        unsigned ww = __ballot_sync(0xffffffffu, v >= 0.8f);
        unsigned ss = __ballot_sync(0xffffffffu, v >= 0.92f);
        rw[wd] = ww;
        if (lane == wd) { myW = ww; myS = ss; }
    }
    if (lane < WPR) {
        g_weak[wb + lane] = myW;
        g_strong[wb + lane] = myS;
        g_auxb[wb + lane] = 0;
    }
#pragma unroll
    for (int wd = 0; wd < WPR; wd++) {
        int idx = base + wd * 32 + lane;
        int par = idx;
        if ((rw[wd] >> lane) & 1) par = idx - runBack(rw, wd, lane);
        g_parent[idx] = par;
    }
}

// K2/K5b: unions with h-1 / z-1 rows, one unite per contiguous overlap segment
template <bool SECOND>
__global__ void k_merge() {
    int t = blockIdx.x * blockDim.x + threadIdx.x;
    int warp = t >> 5, lane = t & 31;
    if (warp >= ROWS) return;
    const unsigned* M = SECOND ? g_mask2 : g_weak;
    int h = warp % HH;
    int z = (warp / HH) % DD;
    int base = warp * WW;
    int wb = warp * WPR;
    bool hasH = (h > 0), hasD = (z > 0);
    if (!hasH && !hasD) return;
    unsigned carryH = 0, carryD = 0;
#pragma unroll
    for (int wd = 0; wd < WPR; wd++) {
        unsigned cur = M[wb + wd];
        if (hasH) {
            unsigned ov = cur & M[wb + wd - WPR];
            unsigned starts = ov & ~((ov << 1) | carryH);
            carryH = ov >> 31;
            if ((starts >> lane) & 1) {
                int p = base + wd * 32 + lane;
                unite(g_parent, p, p - WW);
            }
        }
        if (hasD) {
            unsigned ov = cur & M[wb + wd - WPR * HH];
            unsigned starts = ov & ~((ov << 1) | carryD);
            carryD = ov >> 31;
            if ((starts >> lane) & 1) {
                int p = base + wd * 32 + lane;
                unite(g_parent, p, p - HW);
            }
        }
    }
}

// K3: flatten run starts to roots; set aux bit at root for strong segments
__global__ void k3_flatten_strong() {
    int t = blockIdx.x * blockDim.x + threadIdx.x;
    int warp = t >> 5, lane = t & 31;
    if (warp >= ROWS) return;
    int base = warp * WW;
    int wb = warp * WPR;
    unsigned carry = 0, carryS = 0;
#pragma unroll
    for (int wd = 0; wd < WPR; wd++) {
        unsigned cur = g_weak[wb + wd];
        unsigned starts = cur & ~((cur << 1) | carry);
        carry = cur >> 31;
        if ((starts >> lane) & 1) {
            int s = base + wd * 32 + lane;
            int r = findRoot(g_parent, s);
            if (r != s) g_parent[s] = r;
        }
        unsigned st = g_strong[wb + wd];
        unsigned startsS = st & ~((st << 1) | carryS);
        carryS = st >> 31;
        if ((startsS >> lane) & 1) {
            int p = base + wd * 32 + lane;
            int r = findRoot(g_parent, p);
            atomicOr(&g_auxb[r >> 5], 1u << (r & 31));
        }
    }
}

// K4: hysteresis bits — per word, per set-bit segment: keep iff root flagged
__global__ void k4_hyst() {
    int wi = blockIdx.x * blockDim.x + threadIdx.x;
    if (wi >= NW) return;
    unsigned w = g_weak[wi];
    unsigned hy = 0;
    int p0 = wi * 32;
    while (w) {
        int b = __ffs(w) - 1;
        unsigned x = w >> b;
        int len = (x == 0xffffffffu) ? 32 : (__ffs(~x) - 1);
        unsigned seg = ((len == 32) ? 0xffffffffu : ((1u << len) - 1u)) << b;
        int r = findRoot(g_parent, p0 + b);
        if ((g_auxb[r >> 5] >> (r & 31)) & 1) hy |= seg;
        w &= ~seg;
    }
    g_hyst[wi] = hy;
}

// K5a: z-closing (radius 1, bitwise over z) + pass-2 parent init + cnt clear
__global__ void k5a_close_init() {
    int t = blockIdx.x * blockDim.x + threadIdx.x;
    int warp = t >> 5, lane = t & 31;
    if (warp >= ROWS) return;
    int z = (warp / HH) % DD;
    int base = warp * WW;
    int wb = warp * WPR;
    const int ZOFF = WPR * HH;   // word stride between z planes
    unsigned rw[WPR];
    unsigned my2 = 0;
#pragma unroll
    for (int wd = 0; wd < WPR; wd++) {
        unsigned hm2 = (z >= 2)      ? g_hyst[wb + wd - 2 * ZOFF] : 0u;
        unsigned hm1 = (z >= 1)      ? g_hyst[wb + wd - ZOFF]     : 0u;
        unsigned h0  =                 g_hyst[wb + wd];
        unsigned hp1 = (z <= DD - 2) ? g_hyst[wb + wd + ZOFF]     : 0u;
        unsigned hp2 = (z <= DD - 3) ? g_hyst[wb + wd + 2 * ZOFF] : 0u;
        unsigned dilm = hm2 | hm1 | h0;
        unsigned dil0 = hm1 | h0 | hp1;
        unsigned dilp = h0 | hp1 | hp2;
        unsigned ero = (z ? dilm : 0xffffffffu) & dil0 &
                       ((z < DD - 1) ? dilp : 0xffffffffu);
        rw[wd] = ero;
        if (lane == wd) my2 = ero;
    }
    if (lane < WPR) g_mask2[wb + lane] = my2;
#pragma unroll
    for (int wd = 0; wd < WPR; wd++) {
        int idx = base + wd * 32 + lane;
        int par = idx;
        if ((rw[wd] >> lane) & 1) par = idx - runBack(rw, wd, lane);
        g_parent[idx] = par;
        g_cnt[idx] = 0;
    }
}

// K5c: flatten run starts + atomicAdd(run length) at root
__global__ void k5c_flatten_count() {
    int t = blockIdx.x * blockDim.x + threadIdx.x;
    int warp = t >> 5, lane = t & 31;
    if (warp >= ROWS) return;
    int base = warp * WW;
    int wb = warp * WPR;
    unsigned rw[WPR];
#pragma unroll
    for (int wd = 0; wd < WPR; wd++) rw[wd] = g_mask2[wb + wd];
    unsigned carry = 0;
#pragma unroll
    for (int wd = 0; wd < WPR; wd++) {
        unsigned cur = rw[wd];
        unsigned starts = cur & ~((cur << 1) | carry);
        carry = cur >> 31;
        if ((starts >> lane) & 1) {
            int s = base + wd * 32 + lane;
            int r = findRoot(g_parent, s);
            if (r != s) g_parent[s] = r;
            // run length (may span words within the row)
            int len = 0, wd2 = wd, avail = 32 - lane;
            unsigned x = cur >> lane;
            for (;;) {
                int tt = (x == 0xffffffffu) ? 32 : (__ffs(~x) - 1);
                len += tt;
                if (tt < avail || wd2 == WPR - 1) break;
                wd2++; x = rw[wd2]; avail = 32;
            }
            atomicAdd(&g_cnt[r], len);
        }
    }
}

// K6: final write — per word, per segment: keep iff component size >= 20
__global__ void k6_final(float* __restrict__ out) {
    int wi = blockIdx.x * blockDim.x + threadIdx.x;
    if (wi >= NW) return;
    unsigned m = g_mask2[wi];
    int p0 = wi * 32;
    float o[32];
#pragma unroll
    for (int k = 0; k < 32; k++) o[k] = 0.0f;
    while (m) {
        int b = __ffs(m) - 1;
        unsigned x = m >> b;
        int len = (x == 0xffffffffu) ? 32 : (__ffs(~x) - 1);
        unsigned seg = ((len == 32) ? 0xffffffffu : ((1u << len) - 1u)) << b;
        int r = findRoot(g_parent, p0 + b);
        if (g_cnt[r] >= 20) {
            for (int k = b; k < b + len; k++) o[k] = 1.0f;
        }
        m &= ~seg;
    }
    float4* out4 = reinterpret_cast<float4*>(out) + wi * 8;
#pragma unroll
    for (int k = 0; k < 8; k++)
        out4[k] = make_float4(o[4 * k], o[4 * k + 1], o[4 * k + 2], o[4 * k + 3]);
}

extern "C" void kernel_launch(void* const* d_in, const int* in_sizes, int n_in,
                              void* d_out, int out_size) {
    const float* in = (const float*)d_in[0];
    float* out = (float*)d_out;

    const int TPB = 256;
    const int GRID_ROW = (ROWS * 32) / TPB;   // 6144 (warp per row)
    const int GRID_W   = (NW + TPB - 1) / TPB; // 2304 (thread per word)

    k1_threshold<<<GRID_ROW, TPB>>>(in);
    k_merge<false><<<GRID_ROW, TPB>>>();
    k3_flatten_strong<<<GRID_ROW, TPB>>>();
    k4_hyst<<<GRID_W, TPB>>>();
    k5a_close_init<<<GRID_ROW, TPB>>>();
    k_merge<true><<<GRID_ROW, TPB>>>();
    k5c_flatten_count<<<GRID_ROW, TPB>>>();
    k6_final<<<GRID_W, TPB>>>(out);
}

// round 5
// speedup vs baseline: 1.1176x; 1.0200x over previous
#include <cuda_runtime.h>

#define BB 8
#define DD 16
#define HH 384
#define WW 384
#define HW (HH * WW)            /* 147456 */
#define NBV (DD * HW)           /* 2359296 */
#define NT (BB * NBV)           /* 18874368 voxels */
#define NW (NT / 32)            /* 589824 bit-words */
#define ROWS (BB * DD * HH)     /* 49152 rows of W=384 = 12 words */
#define WPR 12                  /* words per row */

// ---- scratch (__device__ globals; no runtime allocation) ----
__device__ int g_parent[NT];
__device__ int g_cnt[NT];
__device__ unsigned g_weak[NW];
__device__ unsigned g_strong[NW];
__device__ unsigned g_auxb[NW];    // strong-flag bit per root voxel id
__device__ unsigned g_hyst[NW];    // hysteresis-kept mask bits
__device__ unsigned g_mask2[NW];   // closed mask bits

// ---- union-find ----
__device__ __forceinline__ int findRoot(const int* __restrict__ P, int i) {
    int p = P[i];
    while (p != i) { i = p; p = P[i]; }
    return i;
}
__device__ __forceinline__ void unite(int* P, int a, int b) {
    for (;;) {
        a = findRoot(P, a);
        b = findRoot(P, b);
        if (a == b) return;
        if (a > b) { int t = a; a = b; b = t; }
        int old = atomicMin(&P[b], a);
        if (old == b) return;
        b = old;
    }
}

// K1: threshold (ballot) -> bit masks; parent[p] = run start (register-only)
__global__ void k1_threshold(const float* __restrict__ in) {
    int t = blockIdx.x * blockDim.x + threadIdx.x;
    int warp = t >> 5, lane = t & 31;
    if (warp >= ROWS) return;
    int base = warp * WW;
    int wb = warp * WPR;
    unsigned rw[WPR];                     // static indices only -> registers
    unsigned myW = 0, myS = 0;
#pragma unroll
    for (int wd = 0; wd < WPR; wd++) {
        float v = in[base + wd * 32 + lane];
        unsigned ww = __ballot_sync(0xffffffffu, v >= 0.8f);
        unsigned ss = __ballot_sync(0xffffffffu, v >= 0.92f);
        rw[wd] = ww;
        if (lane == wd) { myW = ww; myS = ss; }
    }
    if (lane < WPR) {
        g_weak[wb + lane] = myW;
        g_strong[wb + lane] = myS;
        g_auxb[wb + lane] = 0;
    }
    int run_below = 0;   // consecutive set bits immediately below bit0 of current word
#pragma unroll
    for (int wd = 0; wd < WPR; wd++) {
        unsigned cur = rw[wd];
        int c = lane ? __clz(~(cur << (32 - lane))) : 0;  // ones just below lane, in-word
        if (c == lane) c = lane + run_below;              // run extends across words
        int idx = base + wd * 32 + lane;
        g_parent[idx] = ((cur >> lane) & 1) ? (idx - c) : idx;
        int lo = __clz(~cur);                             // leading ones (top of word)
        run_below = (lo == 32) ? run_below + 32 : lo;
    }
}

// K2/K5b: unions with h-1 / z-1 rows, one unite per contiguous overlap segment
template <bool SECOND>
__global__ void k_merge() {
    int t = blockIdx.x * blockDim.x + threadIdx.x;
    int warp = t >> 5, lane = t & 31;
    if (warp >= ROWS) return;
    const unsigned* M = SECOND ? g_mask2 : g_weak;
    int h = warp % HH;
    int z = (warp / HH) % DD;
    int base = warp * WW;
    int wb = warp * WPR;
    bool hasH = (h > 0), hasD = (z > 0);
    if (!hasH && !hasD) return;
    unsigned carryH = 0, carryD = 0;
#pragma unroll
    for (int wd = 0; wd < WPR; wd++) {
        unsigned cur = M[wb + wd];
        if (hasH) {
            unsigned ov = cur & M[wb + wd - WPR];
            unsigned starts = ov & ~((ov << 1) | carryH);
            carryH = ov >> 31;
            if ((starts >> lane) & 1) {
                int p = base + wd * 32 + lane;
                unite(g_parent, p, p - WW);
            }
        }
        if (hasD) {
            unsigned ov = cur & M[wb + wd - WPR * HH];
            unsigned starts = ov & ~((ov << 1) | carryD);
            carryD = ov >> 31;
            if ((starts >> lane) & 1) {
                int p = base + wd * 32 + lane;
                unite(g_parent, p, p - HW);
            }
        }
    }
}

// K3: flatten run starts to roots; set aux bit at root for strong segments
__global__ void k3_flatten_strong() {
    int t = blockIdx.x * blockDim.x + threadIdx.x;
    int warp = t >> 5, lane = t & 31;
    if (warp >= ROWS) return;
    int base = warp * WW;
    int wb = warp * WPR;
    unsigned carry = 0, carryS = 0;
#pragma unroll
    for (int wd = 0; wd < WPR; wd++) {
        unsigned cur = g_weak[wb + wd];
        unsigned starts = cur & ~((cur << 1) | carry);
        carry = cur >> 31;
        if ((starts >> lane) & 1) {
            int s = base + wd * 32 + lane;
            int r = findRoot(g_parent, s);
            if (r != s) g_parent[s] = r;
        }
        unsigned st = g_strong[wb + wd];
        unsigned startsS = st & ~((st << 1) | carryS);
        carryS = st >> 31;
        if ((startsS >> lane) & 1) {
            int p = base + wd * 32 + lane;
            int r = findRoot(g_parent, p);
            atomicOr(&g_auxb[r >> 5], 1u << (r & 31));
        }
    }
}

// K4: hysteresis bits — per word, per set-bit segment: keep iff root flagged
__global__ void k4_hyst() {
    int wi = blockIdx.x * blockDim.x + threadIdx.x;
    if (wi >= NW) return;
    unsigned w = g_weak[wi];
    unsigned hy = 0;
    int p0 = wi * 32;
    while (w) {
        int b = __ffs(w) - 1;
        unsigned x = w >> b;
        int len = (x == 0xffffffffu) ? 32 : (__ffs(~x) - 1);
        unsigned seg = ((len == 32) ? 0xffffffffu : ((1u << len) - 1u)) << b;
        int r = findRoot(g_parent, p0 + b);
        if ((g_auxb[r >> 5] >> (r & 31)) & 1) hy |= seg;
        w &= ~seg;
    }
    g_hyst[wi] = hy;
}

// K5a: z-closing (radius 1, bitwise over z) + pass-2 parent init + cnt clear
__global__ void k5a_close_init() {
    int t = blockIdx.x * blockDim.x + threadIdx.x;
    int warp = t >> 5, lane = t & 31;
    if (warp >= ROWS) return;
    int z = (warp / HH) % DD;
    int base = warp * WW;
    int wb = warp * WPR;
    const int ZOFF = WPR * HH;   // word stride between z planes
    unsigned rw[WPR];
    unsigned my2 = 0;
#pragma unroll
    for (int wd = 0; wd < WPR; wd++) {
        unsigned hm2 = (z >= 2)      ? g_hyst[wb + wd - 2 * ZOFF] : 0u;
        unsigned hm1 = (z >= 1)      ? g_hyst[wb + wd - ZOFF]     : 0u;
        unsigned h0  =                 g_hyst[wb + wd];
        unsigned hp1 = (z <= DD - 2) ? g_hyst[wb + wd + ZOFF]     : 0u;
        unsigned hp2 = (z <= DD - 3) ? g_hyst[wb + wd + 2 * ZOFF] : 0u;
        unsigned dilm = hm2 | hm1 | h0;
        unsigned dil0 = hm1 | h0 | hp1;
        unsigned dilp = h0 | hp1 | hp2;
        unsigned ero = (z ? dilm : 0xffffffffu) & dil0 &
                       ((z < DD - 1) ? dilp : 0xffffffffu);
        rw[wd] = ero;
        if (lane == wd) my2 = ero;
    }
    if (lane < WPR) g_mask2[wb + lane] = my2;
    int run_below = 0;
#pragma unroll
    for (int wd = 0; wd < WPR; wd++) {
        unsigned cur = rw[wd];
        int c = lane ? __clz(~(cur << (32 - lane))) : 0;
        if (c == lane) c = lane + run_below;
        int idx = base + wd * 32 + lane;
        g_parent[idx] = ((cur >> lane) & 1) ? (idx - c) : idx;
        g_cnt[idx] = 0;
        int lo = __clz(~cur);
        run_below = (lo == 32) ? run_below + 32 : lo;
    }
}

// K5c: flatten run starts + atomicAdd(run length) at root (register-only)
__global__ void k5c_flatten_count() {
    int t = blockIdx.x * blockDim.x + threadIdx.x;
    int warp = t >> 5, lane = t & 31;
    if (warp >= ROWS) return;
    int base = warp * WW;
    int wb = warp * WPR;
    unsigned rw[WPR];
#pragma unroll
    for (int wd = 0; wd < WPR; wd++) rw[wd] = g_mask2[wb + wd];
    // ahead[wd] = consecutive set bits starting at bit0 of word wd (may span words)
    int ahead[WPR + 1];
    ahead[WPR] = 0;
#pragma unroll
    for (int wd = WPR - 1; wd >= 0; wd--) {
        unsigned w = rw[wd];
        int tr = (w == 0xffffffffu) ? 32 : (__ffs(~w) - 1);
        ahead[wd] = (tr == 32) ? 32 + ahead[wd + 1] : tr;
    }
    unsigned carry = 0;
#pragma unroll
    for (int wd = 0; wd < WPR; wd++) {
        unsigned cur = rw[wd];
        unsigned starts = cur & ~((cur << 1) | carry);
        carry = cur >> 31;
        if ((starts >> lane) & 1) {
            int s = base + wd * 32 + lane;
            int r = findRoot(g_parent, s);
            if (r != s) g_parent[s] = r;
            unsigned x = cur >> lane;
            int tt = (x == 0xffffffffu) ? 32 : (__ffs(~x) - 1);
            int len = tt;
            if (lane + tt == 32) len += ahead[wd + 1];   // static index after unroll
            atomicAdd(&g_cnt[r], len);
        }
    }
}

// K6: final write — build keep bitmask per word, expand branchlessly
__global__ void k6_final(float* __restrict__ out) {
    int wi = blockIdx.x * blockDim.x + threadIdx.x;
    if (wi >= NW) return;
    unsigned m = g_mask2[wi];
    unsigned keep = 0;
    int p0 = wi * 32;
    while (m) {
        int b = __ffs(m) - 1;
        unsigned x = m >> b;
        int len = (x == 0xffffffffu) ? 32 : (__ffs(~x) - 1);
        unsigned seg = ((len == 32) ? 0xffffffffu : ((1u << len) - 1u)) << b;
        int r = findRoot(g_parent, p0 + b);
        if (g_cnt[r] >= 20) keep |= seg;
        m &= ~seg;
    }
    float4* out4 = reinterpret_cast<float4*>(out) + wi * 8;
#pragma unroll
    for (int k = 0; k < 8; k++) {
        out4[k] = make_float4(
            ((keep >> (4 * k + 0)) & 1) ? 1.0f : 0.0f,
            ((keep >> (4 * k + 1)) & 1) ? 1.0f : 0.0f,
            ((keep >> (4 * k + 2)) & 1) ? 1.0f : 0.0f,
            ((keep >> (4 * k + 3)) & 1) ? 1.0f : 0.0f);
    }
}

extern "C" void kernel_launch(void* const* d_in, const int* in_sizes, int n_in,
                              void* d_out, int out_size) {
    const float* in = (const float*)d_in[0];
    float* out = (float*)d_out;

    const int TPB = 256;
    const int GRID_ROW = (ROWS * 32) / TPB;    // 6144 (warp per row)
    const int GRID_W   = (NW + TPB - 1) / TPB; // 2304 (thread per word)

    k1_threshold<<<GRID_ROW, TPB>>>(in);
    k_merge<false><<<GRID_ROW, TPB>>>();
    k3_flatten_strong<<<GRID_ROW, TPB>>>();
    k4_hyst<<<GRID_W, TPB>>>();
    k5a_close_init<<<GRID_ROW, TPB>>>();
    k_merge<true><<<GRID_ROW, TPB>>>();
    k5c_flatten_count<<<GRID_ROW, TPB>>>();
    k6_final<<<GRID_W, TPB>>>(out);
}

// round 9
// speedup vs baseline: 1.3672x; 1.2234x over previous
#include <cuda_runtime.h>

#define BB 8
#define DD 16
#define HH 384
#define WW 384
#define HW (HH * WW)            /* 147456 */
#define NBV (DD * HW)           /* 2359296 */
#define NT (BB * NBV)           /* 18874368 voxels */
#define NW (NT / 32)            /* 589824 bit-words */
#define ROWS (BB * DD * HH)     /* 49152 rows of W=384 */
#define WPR 12                  /* words per row */
#define SLOTS 192               /* max runs per row (ceil(W/2)) */
#define NR (ROWS * SLOTS)       /* 9437184 run slots */

// ---- scratch (__device__ globals; no runtime allocation) ----
__device__ int g_parent[NR];         // union-find over run slots (36MB, sparse-touched)
__device__ int g_cnt[NR];            // component sizes at root runs
__device__ unsigned g_auxb[NR / 32]; // strong-flag bit per root run (1.2MB)
__device__ unsigned g_weak[NW];
__device__ unsigned g_strong[NW];
__device__ unsigned g_hyst[NW];
__device__ unsigned g_mask2[NW];

// ---- union-find ----
__device__ __forceinline__ int findRoot(const int* __restrict__ P, int i) {
    int p = P[i];
    while (p != i) { i = p; p = P[i]; }
    return i;
}
__device__ __forceinline__ void unite(int* P, int a, int b) {
    for (;;) {
        a = findRoot(P, a);
        b = findRoot(P, b);
        if (a == b) return;
        if (a > b) { int t = a; a = b; b = t; }
        int old = atomicMin(&P[b], a);
        if (old == b) return;
        b = old;
    }
}

__device__ __forceinline__ unsigned lemask(int lane) { return (2u << lane) - 1u; } // bits 0..lane
__device__ __forceinline__ unsigned ltmask(int lane) { return (1u << lane) - 1u; } // bits 0..lane-1

// K1: threshold via ballot -> bit masks; init this row's run-parent slots + aux
__global__ void k1_threshold(const float* __restrict__ in) {
    int t = blockIdx.x * blockDim.x + threadIdx.x;
    int row = t >> 5, lane = t & 31;
    if (row >= ROWS) return;
    int base = row * WW, wb = row * WPR, rbase = row * SLOTS;
    unsigned myW = 0, myS = 0;
#pragma unroll
    for (int wd = 0; wd < WPR; wd++) {
        float v = in[base + wd * 32 + lane];
        unsigned ww = __ballot_sync(0xffffffffu, v >= 0.8f);
        unsigned ss = __ballot_sync(0xffffffffu, v >= 0.92f);
        if (lane == wd) { myW = ww; myS = ss; }
    }
    if (lane < WPR) { g_weak[wb + lane] = myW; g_strong[wb + lane] = myS; }
#pragma unroll
    for (int k = 0; k < SLOTS / 32; k++) {
        int ri = rbase + k * 32 + lane;
        g_parent[ri] = ri;
    }
    if (lane < SLOTS / 32) g_auxb[row * (SLOTS / 32) + lane] = 0;
}

// K2/K5b: one unite per contiguous overlap segment with h-1 / z-1 rows,
// operating on run-ids computed from popcount ranks.
template <bool SECOND>
__global__ void k2_merge() {
    int t = blockIdx.x * blockDim.x + threadIdx.x;
    int row = t >> 5, lane = t & 31;
    if (row >= ROWS) return;
    const unsigned* M = SECOND ? g_mask2 : g_weak;
    int h = row % HH, z = (row / HH) % DD;
    bool hasH = (h > 0), hasD = (z > 0);
    if (!hasH && !hasD) return;
    int wb = row * WPR, rbase = row * SLOTS;
    int nbH = (row - 1) * SLOTS, nbD = (row - HH) * SLOTS;
    unsigned cC = 0, cH = 0, cD = 0, cOH = 0, cOD = 0;
    int cumC = 0, cumH = 0, cumD = 0;
#pragma unroll
    for (int wd = 0; wd < WPR; wd++) {
        unsigned cur = M[wb + wd];
        unsigned sC = cur & ~((cur << 1) | cC);
        if (hasH) {
            unsigned nh = M[wb + wd - WPR];
            unsigned sH = nh & ~((nh << 1) | cH);
            unsigned ov = cur & nh;
            unsigned so = ov & ~((ov << 1) | cOH);
            if ((so >> lane) & 1) {
                int ra = rbase + cumC + __popc(sC & lemask(lane)) - 1;
                int rb = nbH + cumH + __popc(sH & lemask(lane)) - 1;
                unite(g_parent, ra, rb);
            }
            cH = nh >> 31; cOH = ov >> 31; cumH += __popc(sH);
        }
        if (hasD) {
            unsigned nd = M[wb + wd - WPR * HH];
            unsigned sD = nd & ~((nd << 1) | cD);
            unsigned ov = cur & nd;
            unsigned so = ov & ~((ov << 1) | cOD);
            if ((so >> lane) & 1) {
                int ra = rbase + cumC + __popc(sC & lemask(lane)) - 1;
                int rb = nbD + cumD + __popc(sD & lemask(lane)) - 1;
                unite(g_parent, ra, rb);
            }
            cD = nd >> 31; cOD = ov >> 31; cumD += __popc(sD);
        }
        cC = cur >> 31; cumC += __popc(sC);
    }
}

// K3: flatten every run; set aux bit at root for runs containing strong bits
__global__ void k3_flatten_strong() {
    int t = blockIdx.x * blockDim.x + threadIdx.x;
    int row = t >> 5, lane = t & 31;
    if (row >= ROWS) return;
    int wb = row * WPR, rbase = row * SLOTS;
    unsigned cC = 0, cS = 0;
    int cumC = 0;
#pragma unroll
    for (int wd = 0; wd < WPR; wd++) {
        unsigned cur = g_weak[wb + wd];
        unsigned sC = cur & ~((cur << 1) | cC);
        if ((sC >> lane) & 1) {
            int ri = rbase + cumC + __popc(sC & ltmask(lane));
            int r = findRoot(g_parent, ri);
            if (r != ri) g_parent[ri] = r;
        }
        unsigned st = g_strong[wb + wd];
        unsigned sS = st & ~((st << 1) | cS);
        if ((sS >> lane) & 1) {
            int ri = rbase + cumC + __popc(sC & lemask(lane)) - 1;  // containing weak run
            int r = findRoot(g_parent, ri);
            atomicOr(&g_auxb[r >> 5], 1u << (r & 31));
        }
        cC = cur >> 31; cS = st >> 31; cumC += __popc(sC);
    }
}

// K4: hysteresis — per run start: root flagged? then expand to all bits via
// ballot + clz (cross-word carry for runs spanning words).
__global__ void k4_hyst() {
    int t = blockIdx.x * blockDim.x + threadIdx.x;
    int row = t >> 5, lane = t & 31;
    if (row >= ROWS) return;
    int wb = row * WPR, rbase = row * SLOTS;
    unsigned cC = 0, carryKept = 0, myHy = 0;
    int cumC = 0;
#pragma unroll
    for (int wd = 0; wd < WPR; wd++) {
        unsigned cur = g_weak[wb + wd];
        unsigned sC = cur & ~((cur << 1) | cC);
        int keptBit = 0;
        if ((sC >> lane) & 1) {
            int ri = rbase + cumC + __popc(sC & ltmask(lane));
            int r = findRoot(g_parent, ri);
            keptBit = (g_auxb[r >> 5] >> (r & 31)) & 1;
        }
        unsigned keptStarts = __ballot_sync(0xffffffffu, keptBit);
        unsigned inS = sC & lemask(lane);
        unsigned mk = inS ? ((keptStarts >> (31 - __clz(inS))) & 1) : carryKept;
        unsigned hy = __ballot_sync(0xffffffffu, ((cur >> lane) & 1) && mk);
        if (lane == wd) myHy = hy;
        if (cur >> 31)
            carryKept = sC ? ((keptStarts >> (31 - __clz(sC))) & 1) : carryKept;
        else
            carryKept = 0;
        cC = cur >> 31; cumC += __popc(sC);
    }
    if (lane < WPR) g_hyst[wb + lane] = myHy;
}

// K5a: z-closing (radius 1, bitwise) + pass-2 run-parent/cnt init for this row
__global__ void k5a_close() {
    int t = blockIdx.x * blockDim.x + threadIdx.x;
    int row = t >> 5, lane = t & 31;
    if (row >= ROWS) return;
    int z = (row / HH) % DD;
    int wb = row * WPR, rbase = row * SLOTS;
    const int ZOFF = WPR * HH;
    unsigned my2 = 0;
#pragma unroll
    for (int wd = 0; wd < WPR; wd++) {
        unsigned hm2 = (z >= 2)      ? g_hyst[wb + wd - 2 * ZOFF] : 0u;
        unsigned hm1 = (z >= 1)      ? g_hyst[wb + wd - ZOFF]     : 0u;
        unsigned h0  =                 g_hyst[wb + wd];
        unsigned hp1 = (z <= DD - 2) ? g_hyst[wb + wd + ZOFF]     : 0u;
        unsigned hp2 = (z <= DD - 3) ? g_hyst[wb + wd + 2 * ZOFF] : 0u;
        unsigned dilm = hm2 | hm1 | h0;
        unsigned dil0 = hm1 | h0 | hp1;
        unsigned dilp = h0 | hp1 | hp2;
        unsigned ero = (z ? dilm : 0xffffffffu) & dil0 &
                       ((z < DD - 1) ? dilp : 0xffffffffu);
        if (lane == wd) my2 = ero;
    }
    if (lane < WPR) g_mask2[wb + lane] = my2;
#pragma unroll
    for (int k = 0; k < SLOTS / 32; k++) {
        int ri = rbase + k * 32 + lane;
        g_parent[ri] = ri;
        g_cnt[ri] = 0;
    }
}

// K5c: flatten every run + atomicAdd(run length) at root
__global__ void k5c_flatten_count() {
    int t = blockIdx.x * blockDim.x + threadIdx.x;
    int row = t >> 5, lane = t & 31;
    if (row >= ROWS) return;
    int wb = row * WPR, rbase = row * SLOTS;
    unsigned rw[WPR];
#pragma unroll
    for (int wd = 0; wd < WPR; wd++) rw[wd] = g_mask2[wb + wd];
    int ahead[WPR + 1];
    ahead[WPR] = 0;
#pragma unroll
    for (int wd = WPR - 1; wd >= 0; wd--) {
        unsigned w = rw[wd];
        int tr = (w == 0xffffffffu) ? 32 : (__ffs(~w) - 1);
        ahead[wd] = (tr == 32) ? 32 + ahead[wd + 1] : tr;
    }
    unsigned cC = 0;
    int cumC = 0;
#pragma unroll
    for (int wd = 0; wd < WPR; wd++) {
        unsigned cur = rw[wd];
        unsigned sC = cur & ~((cur << 1) | cC);
        if ((sC >> lane) & 1) {
            int ri = rbase + cumC + __popc(sC & ltmask(lane));
            int r = findRoot(g_parent, ri);
            if (r != ri) g_parent[ri] = r;
            unsigned x = cur >> lane;
            int tt = (x == 0xffffffffu) ? 32 : (__ffs(~x) - 1);
            int len = tt;
            if (lane + tt == 32) len += ahead[wd + 1];
            atomicAdd(&g_cnt[r], len);
        }
        cC = cur >> 31; cumC += __popc(sC);
    }
}

// K6: per run start: size >= 20? expand kept flag to all bits; coalesced stores
__global__ void k6_final(float* __restrict__ out) {
    int t = blockIdx.x * blockDim.x + threadIdx.x;
    int row = t >> 5, lane = t & 31;
    if (row >= ROWS) return;
    int base = row * WW, wb = row * WPR, rbase = row * SLOTS;
    unsigned cC = 0, carryKept = 0;
    int cumC = 0;
#pragma unroll
    for (int wd = 0; wd < WPR; wd++) {
        unsigned cur = g_mask2[wb + wd];
        unsigned sC = cur & ~((cur << 1) | cC);
        int keptBit = 0;
        if ((sC >> lane) & 1) {
            int ri = rbase + cumC + __popc(sC & ltmask(lane));
            int r = findRoot(g_parent, ri);   // flattened in k5c: 1 hop
            keptBit = (g_cnt[r] >= 20) ? 1 : 0;
        }
        unsigned keptStarts = __ballot_sync(0xffffffffu, keptBit);
        unsigned inS = sC & lemask(lane);
        unsigned mk = inS ? ((keptStarts >> (31 - __clz(inS))) & 1) : carryKept;
        bool kb = ((cur >> lane) & 1) && mk;
        out[base + wd * 32 + lane] = kb ? 1.0f : 0.0f;
        if (cur >> 31)
            carryKept = sC ? ((keptStarts >> (31 - __clz(sC))) & 1) : carryKept;
        else
            carryKept = 0;
        cC = cur >> 31; cumC += __popc(sC);
    }
}

extern "C" void kernel_launch(void* const* d_in, const int* in_sizes, int n_in,
                              void* d_out, int out_size) {
    const float* in = (const float*)d_in[0];
    float* out = (float*)d_out;

    const int TPB = 256;
    const int GRID_ROW = (ROWS * 32) / TPB;   // 6144 blocks, warp per row

    k1_threshold<<<GRID_ROW, TPB>>>(in);
    k2_merge<false><<<GRID_ROW, TPB>>>();
    k3_flatten_strong<<<GRID_ROW, TPB>>>();
    k4_hyst<<<GRID_ROW, TPB>>>();
    k5a_close<<<GRID_ROW, TPB>>>();
    k2_merge<true><<<GRID_ROW, TPB>>>();
    k5c_flatten_count<<<GRID_ROW, TPB>>>();
    k6_final<<<GRID_ROW, TPB>>>(out);
}

// round 12
// speedup vs baseline: 2.6379x; 1.9293x over previous
#include <cuda_runtime.h>

#define BB 8
#define DD 16
#define HH 384
#define WW 384
#define HW (HH * WW)            /* 147456 */
#define NBV (DD * HW)           /* 2359296 */
#define NT (BB * NBV)           /* 18874368 voxels */
#define NW (NT / 32)            /* 589824 bit-words */
#define ROWS (BB * DD * HH)     /* 49152 rows of W=384 */
#define WPR 12                  /* words per row */
#define SLOTS 192               /* max runs per row */
#define NR (ROWS * SLOTS)       /* 9437184 run slots */

// ---- scratch (__device__ globals; no runtime allocation) ----
__device__ int g_parent[NR];
__device__ int g_cnt[NR];
__device__ unsigned g_auxb[NR / 32];
__device__ unsigned g_weak[NW];
__device__ unsigned g_strong[NW];
__device__ unsigned g_hyst[NW];
__device__ unsigned g_mask2[NW];
__device__ unsigned char g_pref[NW];  // run starts in row before this word

__device__ __forceinline__ int findRoot(const int* __restrict__ P, int i) {
    int p = P[i];
    while (p != i) { i = p; p = P[i]; }
    return i;
}
__device__ __forceinline__ void unite(int* P, int a, int b) {
    for (;;) {
        a = findRoot(P, a);
        b = findRoot(P, b);
        if (a == b) return;
        if (a > b) { int t = a; a = b; b = t; }
        int old = atomicMin(&P[b], a);
        if (old == b) return;
        b = old;
    }
}
__device__ __forceinline__ unsigned lemask(int lane) { return (2u << lane) - 1u; }
__device__ __forceinline__ unsigned ltmask(int lane) { return (1u << lane) - 1u; }

// K1 (warp/row): thresholds -> masks, run prefix, parent + aux init
__global__ void k1_threshold(const float* __restrict__ in) {
    int t = blockIdx.x * blockDim.x + threadIdx.x;
    int row = t >> 5, lane = t & 31;
    if (row >= ROWS) return;
    int base = row * WW, wb = row * WPR, rbase = row * SLOTS;
    unsigned myW = 0, myS = 0;
#pragma unroll
    for (int wd = 0; wd < WPR; wd++) {
        float v = in[base + wd * 32 + lane];
        unsigned ww = __ballot_sync(0xffffffffu, v >= 0.8f);
        unsigned ss = __ballot_sync(0xffffffffu, v >= 0.92f);
        if (lane == wd) { myW = ww; myS = ss; }
    }
    unsigned prev = __shfl_up_sync(0xffffffffu, myW, 1);
    if (lane == 0) prev = 0;
    unsigned sC = myW & ~((myW << 1) | (prev >> 31));
    int cnt = __popc(sC);
    int x = cnt;
#pragma unroll
    for (int o = 1; o < 32; o <<= 1) {
        int y = __shfl_up_sync(0xffffffffu, x, o);
        if (lane >= o) x += y;
    }
    if (lane < WPR) {
        g_weak[wb + lane] = myW;
        g_strong[wb + lane] = myS;
        g_pref[wb + lane] = (unsigned char)(x - cnt);
    }
#pragma unroll
    for (int k = 0; k < SLOTS / 32; k++) {
        int ri = rbase + k * 32 + lane;
        g_parent[ri] = ri;
    }
    if (lane < SLOTS / 32) g_auxb[row * (SLOTS / 32) + lane] = 0;
}

// K2/K5b (thread/word): one unite per overlap segment with h-1 / z-1 rows
template <bool SECOND>
__global__ void k2_merge() {
    int wi = blockIdx.x * blockDim.x + threadIdx.x;
    if (wi >= NW) return;
    int row = wi / WPR, wd = wi - row * WPR;
    const unsigned* M = SECOND ? g_mask2 : g_weak;
    unsigned cur = M[wi];
    if (!cur) return;
    int h = row % HH, z = (row / HH) % DD;
    bool hasH = (h > 0), hasD = (z > 0);
    if (!hasH && !hasD) return;
    unsigned prevC = wd ? M[wi - 1] : 0;
    unsigned sC = cur & ~((cur << 1) | (prevC >> 31));
    int pC = g_pref[wi];
    int rbase = row * SLOTS;
    if (hasH) {
        unsigned nh = M[wi - WPR];
        unsigned ov = cur & nh;
        if (ov) {
            unsigned prevH = wd ? M[wi - 1 - WPR] : 0;
            unsigned sH = nh & ~((nh << 1) | (prevH >> 31));
            unsigned so = ov & ~((ov << 1) | ((prevC & prevH) >> 31));
            int pH = g_pref[wi - WPR];
            int nb = (row - 1) * SLOTS;
            while (so) {
                int b = __ffs(so) - 1; so &= so - 1;
                int ra = rbase + pC + __popc(sC & lemask(b)) - 1;
                int rb = nb + pH + __popc(sH & lemask(b)) - 1;
                unite(g_parent, ra, rb);
            }
        }
    }
    if (hasD) {
        unsigned nd = M[wi - WPR * HH];
        unsigned ov = cur & nd;
        if (ov) {
            unsigned prevD = wd ? M[wi - 1 - WPR * HH] : 0;
            unsigned sD = nd & ~((nd << 1) | (prevD >> 31));
            unsigned so = ov & ~((ov << 1) | ((prevC & prevD) >> 31));
            int pD = g_pref[wi - WPR * HH];
            int nb = (row - HH) * SLOTS;
            while (so) {
                int b = __ffs(so) - 1; so &= so - 1;
                int ra = rbase + pC + __popc(sC & lemask(b)) - 1;
                int rb = nb + pD + __popc(sD & lemask(b)) - 1;
                unite(g_parent, ra, rb);
            }
        }
    }
}

// K3 (thread/word): flatten run starts; flag roots of strong-containing runs
__global__ void k3_flatten_strong() {
    int wi = blockIdx.x * blockDim.x + threadIdx.x;
    if (wi >= NW) return;
    unsigned cur = g_weak[wi];
    if (!cur) return;
    int row = wi / WPR, wd = wi - row * WPR;
    unsigned prevC = wd ? g_weak[wi - 1] : 0;
    unsigned sC = cur & ~((cur << 1) | (prevC >> 31));
    int pC = g_pref[wi];
    int rbase = row * SLOTS;
    unsigned s = sC;
    while (s) {
        int b = __ffs(s) - 1; s &= s - 1;
        int ri = rbase + pC + __popc(sC & ltmask(b));
        int r = findRoot(g_parent, ri);
        if (r != ri) g_parent[ri] = r;
    }
    unsigned st = g_strong[wi];
    if (st) {
        unsigned prevS = wd ? g_strong[wi - 1] : 0;
        unsigned sS = st & ~((st << 1) | (prevS >> 31));
        while (sS) {
            int b = __ffs(sS) - 1; sS &= sS - 1;
            int ri = rbase + pC + __popc(sC & lemask(b)) - 1;
            int r = findRoot(g_parent, ri);
            atomicOr(&g_auxb[r >> 5], 1u << (r & 31));
        }
    }
}

// K4 (thread/word): hysteresis expansion per in-word segment
__global__ void k4_hyst() {
    int wi = blockIdx.x * blockDim.x + threadIdx.x;
    if (wi >= NW) return;
    unsigned cur = g_weak[wi];
    unsigned hy = 0;
    if (cur) {
        int row = wi / WPR, wd = wi - row * WPR;
        unsigned prevC = wd ? g_weak[wi - 1] : 0;
        unsigned sC = cur & ~((cur << 1) | (prevC >> 31));
        int pC = g_pref[wi];
        int rbase = row * SLOTS;
        unsigned m = cur;
        while (m) {
            int b = __ffs(m) - 1;
            unsigned x = m >> b;
            int len = (x == 0xffffffffu) ? 32 : (__ffs(~x) - 1);
            unsigned seg = ((len == 32) ? 0xffffffffu : ((1u << len) - 1u)) << b;
            int ri = rbase + pC + __popc(sC & lemask(b)) - 1;
            int r = findRoot(g_parent, ri);
            if ((g_auxb[r >> 5] >> (r & 31)) & 1) hy |= seg;
            m &= ~seg;
        }
    }
    g_hyst[wi] = hy;
}

// K5a (warp/row): z-closing + pass-2 prefix + parent/cnt init
__global__ void k5a_close() {
    int t = blockIdx.x * blockDim.x + threadIdx.x;
    int row = t >> 5, lane = t & 31;
    if (row >= ROWS) return;
    int z = (row / HH) % DD;
    int wb = row * WPR, rbase = row * SLOTS;
    const int ZOFF = WPR * HH;
    unsigned my2 = 0;
#pragma unroll
    for (int wd = 0; wd < WPR; wd++) {
        unsigned hm2 = (z >= 2)      ? g_hyst[wb + wd - 2 * ZOFF] : 0u;
        unsigned hm1 = (z >= 1)      ? g_hyst[wb + wd - ZOFF]     : 0u;
        unsigned h0  =                 g_hyst[wb + wd];
        unsigned hp1 = (z <= DD - 2) ? g_hyst[wb + wd + ZOFF]     : 0u;
        unsigned hp2 = (z <= DD - 3) ? g_hyst[wb + wd + 2 * ZOFF] : 0u;
        unsigned dilm = hm2 | hm1 | h0;
        unsigned dil0 = hm1 | h0 | hp1;
        unsigned dilp = h0 | hp1 | hp2;
        unsigned ero = (z ? dilm : 0xffffffffu) & dil0 &
                       ((z < DD - 1) ? dilp : 0xffffffffu);
        if (lane == wd) my2 = ero;
    }
    unsigned prev = __shfl_up_sync(0xffffffffu, my2, 1);
    if (lane == 0) prev = 0;
    unsigned sC = my2 & ~((my2 << 1) | (prev >> 31));
    int cnt = __popc(sC);
    int x = cnt;
#pragma unroll
    for (int o = 1; o < 32; o <<= 1) {
        int y = __shfl_up_sync(0xffffffffu, x, o);
        if (lane >= o) x += y;
    }
    if (lane < WPR) {
        g_mask2[wb + lane] = my2;
        g_pref[wb + lane] = (unsigned char)(x - cnt);
    }
#pragma unroll
    for (int k = 0; k < SLOTS / 32; k++) {
        int ri = rbase + k * 32 + lane;
        g_parent[ri] = ri;
        g_cnt[ri] = 0;
    }
}

// K5c (thread/word): flatten + per-word-piece length accumulation at root
__global__ void k5c_flatten_count() {
    int wi = blockIdx.x * blockDim.x + threadIdx.x;
    if (wi >= NW) return;
    unsigned cur = g_mask2[wi];
    if (!cur) return;
    int row = wi / WPR, wd = wi - row * WPR;
    unsigned prevC = wd ? g_mask2[wi - 1] : 0;
    unsigned sC = cur & ~((cur << 1) | (prevC >> 31));
    int pC = g_pref[wi];
    int rbase = row * SLOTS;
    unsigned m = cur;
    while (m) {
        int b = __ffs(m) - 1;
        unsigned x = m >> b;
        int len = (x == 0xffffffffu) ? 32 : (__ffs(~x) - 1);
        unsigned seg = ((len == 32) ? 0xffffffffu : ((1u << len) - 1u)) << b;
        int ri = rbase + pC + __popc(sC & lemask(b)) - 1;
        int r = findRoot(g_parent, ri);
        if (((sC >> b) & 1) && r != ri) g_parent[ri] = r;
        atomicAdd(&g_cnt[r], len);
        m &= ~seg;
    }
}

// K6 (thread/word): keep mask per word, float4 stores
__global__ void k6_final(float* __restrict__ out) {
    int wi = blockIdx.x * blockDim.x + threadIdx.x;
    if (wi >= NW) return;
    unsigned cur = g_mask2[wi];
    unsigned keep = 0;
    if (cur) {
        int row = wi / WPR, wd = wi - row * WPR;
        unsigned prevC = wd ? g_mask2[wi - 1] : 0;
        unsigned sC = cur & ~((cur << 1) | (prevC >> 31));
        int pC = g_pref[wi];
        int rbase = row * SLOTS;
        unsigned m = cur;
        while (m) {
            int b = __ffs(m) - 1;
            unsigned x = m >> b;
            int len = (x == 0xffffffffu) ? 32 : (__ffs(~x) - 1);
            unsigned seg = ((len == 32) ? 0xffffffffu : ((1u << len) - 1u)) << b;
            int ri = rbase + pC + __popc(sC & lemask(b)) - 1;
            int r = findRoot(g_parent, ri);
            if (g_cnt[r] >= 20) keep |= seg;
            m &= ~seg;
        }
    }
    float4* out4 = reinterpret_cast<float4*>(out) + wi * 8;
#pragma unroll
    for (int k = 0; k < 8; k++) {
        out4[k] = make_float4(
            ((keep >> (4 * k + 0)) & 1) ? 1.0f : 0.0f,
            ((keep >> (4 * k + 1)) & 1) ? 1.0f : 0.0f,
            ((keep >> (4 * k + 2)) & 1) ? 1.0f : 0.0f,
            ((keep >> (4 * k + 3)) & 1) ? 1.0f : 0.0f);
    }
}

extern "C" void kernel_launch(void* const* d_in, const int* in_sizes, int n_in,
                              void* d_out, int out_size) {
    const float* in = (const float*)d_in[0];
    float* out = (float*)d_out;

    const int TPB = 256;
    const int GRID_ROW = (ROWS * 32) / TPB;     // 6144 (warp per row)
    const int GRID_W   = (NW + TPB - 1) / TPB;  // 2304 (thread per word)

    k1_threshold<<<GRID_ROW, TPB>>>(in);
    k2_merge<false><<<GRID_W, TPB>>>();
    k3_flatten_strong<<<GRID_W, TPB>>>();
    k4_hyst<<<GRID_W, TPB>>>();
    k5a_close<<<GRID_ROW, TPB>>>();
    k2_merge<true><<<GRID_W, TPB>>>();
    k5c_flatten_count<<<GRID_W, TPB>>>();
    k6_final<<<GRID_W, TPB>>>(out);
}

// round 13
// speedup vs baseline: 2.9675x; 1.1250x over previous
#include <cuda_runtime.h>

#define BB 8
#define DD 16
#define HH 384
#define WW 384
#define HW (HH * WW)            /* 147456 */
#define NBV (DD * HW)           /* 2359296 */
#define NT (BB * NBV)           /* 18874368 voxels */
#define NW (NT / 32)            /* 589824 bit-words */
#define ROWS (BB * DD * HH)     /* 49152 rows of W=384 */
#define WPR 12                  /* words per row */
#define SLOTS 192               /* max runs per row */
#define NR (ROWS * SLOTS)       /* 9437184 run slots */

// ---- scratch (__device__ globals; no runtime allocation) ----
__device__ int g_parent[NR];
__device__ int g_cnt[NR];
__device__ unsigned g_auxb[NR / 32];
__device__ unsigned g_weak[NW];
__device__ unsigned g_strong[NW];
__device__ unsigned g_hyst[NW];
__device__ unsigned g_mask2[NW];
__device__ unsigned char g_pref[NW];  // run starts in row before this word

__device__ __forceinline__ int findRoot(const int* __restrict__ P, int i) {
    int p = P[i];
    while (p != i) { i = p; p = P[i]; }
    return i;
}
__device__ __forceinline__ void unite(int* P, int a, int b) {
    for (;;) {
        a = findRoot(P, a);
        b = findRoot(P, b);
        if (a == b) return;
        if (a > b) { int t = a; a = b; b = t; }
        int old = atomicMin(&P[b], a);
        if (old == b) return;
        b = old;
    }
}
__device__ __forceinline__ unsigned lemask(int b) { return (2u << b) - 1u; }
__device__ __forceinline__ unsigned ltmask(int b) { return (1u << b) - 1u; }

// K1 (warp/row): thresholds -> masks, run prefix, PARTIAL parent + aux init
__global__ void k1_threshold(const float* __restrict__ in) {
    int t = blockIdx.x * blockDim.x + threadIdx.x;
    int row = t >> 5, lane = t & 31;
    if (row >= ROWS) return;
    int base = row * WW, wb = row * WPR, rbase = row * SLOTS;
    unsigned myW = 0, myS = 0;
#pragma unroll
    for (int wd = 0; wd < WPR; wd++) {
        float v = in[base + wd * 32 + lane];
        unsigned ww = __ballot_sync(0xffffffffu, v >= 0.8f);
        unsigned ss = __ballot_sync(0xffffffffu, v >= 0.92f);
        if (lane == wd) { myW = ww; myS = ss; }
    }
    unsigned prev = __shfl_up_sync(0xffffffffu, myW, 1);
    if (lane == 0) prev = 0;
    unsigned sC = myW & ~((myW << 1) | (prev >> 31));
    int cnt = __popc(sC);
    int x = cnt;
#pragma unroll
    for (int o = 1; o < 32; o <<= 1) {
        int y = __shfl_up_sync(0xffffffffu, x, o);
        if (lane >= o) x += y;
    }
    if (lane < WPR) {
        g_weak[wb + lane] = myW;
        g_strong[wb + lane] = myS;
        g_pref[wb + lane] = (unsigned char)(x - cnt);
    }
    int nruns = __shfl_sync(0xffffffffu, x, 31);
    int initSlots = (nruns + 31) & ~31;
    for (int o = lane; o < initSlots; o += 32)
        g_parent[rbase + o] = rbase + o;
    if (lane < (initSlots >> 5))
        g_auxb[row * (SLOTS / 32) + lane] = 0;
}

// K2/K5b (thread/word): one unite per overlap segment with h-1 / z-1 rows
template <bool SECOND>
__global__ void k2_merge() {
    int wi = blockIdx.x * blockDim.x + threadIdx.x;
    if (wi >= NW) return;
    int row = wi / WPR, wd = wi - row * WPR;
    const unsigned* __restrict__ M = SECOND ? g_mask2 : g_weak;
    unsigned cur = M[wi];
    if (!cur) return;
    int h = row % HH, z = (row / HH) % DD;
    bool hasH = (h > 0), hasD = (z > 0);
    if (!hasH && !hasD) return;
    unsigned prevC = wd ? M[wi - 1] : 0;
    unsigned sC = cur & ~((cur << 1) | (prevC >> 31));
    int pC = g_pref[wi];
    int rbase = row * SLOTS;
    if (hasH) {
        unsigned nh = M[wi - WPR];
        unsigned ov = cur & nh;
        if (ov) {
            unsigned prevH = wd ? M[wi - 1 - WPR] : 0;
            unsigned sH = nh & ~((nh << 1) | (prevH >> 31));
            unsigned so = ov & ~((ov << 1) | ((prevC & prevH) >> 31));
            int pH = g_pref[wi - WPR];
            int nb = (row - 1) * SLOTS;
            while (so) {
                int b = __ffs(so) - 1; so &= so - 1;
                int ra = rbase + pC + __popc(sC & lemask(b)) - 1;
                int rb = nb + pH + __popc(sH & lemask(b)) - 1;
                unite(g_parent, ra, rb);
            }
        }
    }
    if (hasD) {
        unsigned nd = M[wi - WPR * HH];
        unsigned ov = cur & nd;
        if (ov) {
            unsigned prevD = wd ? M[wi - 1 - WPR * HH] : 0;
            unsigned sD = nd & ~((nd << 1) | (prevD >> 31));
            unsigned so = ov & ~((ov << 1) | ((prevC & prevD) >> 31));
            int pD = g_pref[wi - WPR * HH];
            int nb = (row - HH) * SLOTS;
            while (so) {
                int b = __ffs(so) - 1; so &= so - 1;
                int ra = rbase + pC + __popc(sC & lemask(b)) - 1;
                int rb = nb + pD + __popc(sD & lemask(b)) - 1;
                unite(g_parent, ra, rb);
            }
        }
    }
}

// K3 (thread/word): flag roots of strong-containing runs (no flatten sweep)
__global__ void k3_strong() {
    int wi = blockIdx.x * blockDim.x + threadIdx.x;
    if (wi >= NW) return;
    unsigned st = g_strong[wi];
    if (!st) return;
    int row = wi / WPR, wd = wi - row * WPR;
    unsigned cur = g_weak[wi];
    unsigned prevC = wd ? g_weak[wi - 1] : 0;
    unsigned sC = cur & ~((cur << 1) | (prevC >> 31));
    int pC = g_pref[wi];
    int rbase = row * SLOTS;
    unsigned prevS = wd ? g_strong[wi - 1] : 0;
    unsigned sS = st & ~((st << 1) | (prevS >> 31));
    while (sS) {
        int b = __ffs(sS) - 1; sS &= sS - 1;
        int ri = rbase + pC + __popc(sC & lemask(b)) - 1;
        int r = findRoot(g_parent, ri);
        atomicOr(&g_auxb[r >> 5], 1u << (r & 31));
    }
}

// K4 (thread/word): hysteresis expansion per in-word segment
__global__ void k4_hyst() {
    int wi = blockIdx.x * blockDim.x + threadIdx.x;
    if (wi >= NW) return;
    unsigned cur = g_weak[wi];
    unsigned hy = 0;
    if (cur) {
        int row = wi / WPR, wd = wi - row * WPR;
        unsigned prevC = wd ? g_weak[wi - 1] : 0;
        unsigned sC = cur & ~((cur << 1) | (prevC >> 31));
        int pC = g_pref[wi];
        int rbase = row * SLOTS;
        unsigned m = cur;
        while (m) {
            int b = __ffs(m) - 1;
            unsigned x = m >> b;
            int len = (x == 0xffffffffu) ? 32 : (__ffs(~x) - 1);
            unsigned seg = ((len == 32) ? 0xffffffffu : ((1u << len) - 1u)) << b;
            int ri = rbase + pC + __popc(sC & lemask(b)) - 1;
            int r = findRoot(g_parent, ri);
            if ((g_auxb[r >> 5] >> (r & 31)) & 1) hy |= seg;
            m &= ~seg;
        }
    }
    g_hyst[wi] = hy;
}

// K5a (warp/row): z-closing (lane-parallel loads) + prefix + PARTIAL init
__global__ void k5a_close() {
    int t = blockIdx.x * blockDim.x + threadIdx.x;
    int row = t >> 5, lane = t & 31;
    if (row >= ROWS) return;
    int z = (row / HH) % DD;
    int wb = row * WPR, rbase = row * SLOTS;
    const int ZOFF = WPR * HH;
    unsigned my2 = 0;
    if (lane < WPR) {
        int wi = wb + lane;
        unsigned h0  = g_hyst[wi];
        unsigned hm1 = (z >= 1)      ? g_hyst[wi - ZOFF]     : 0u;
        unsigned hm2 = (z >= 2)      ? g_hyst[wi - 2 * ZOFF] : 0u;
        unsigned hp1 = (z <= DD - 2) ? g_hyst[wi + ZOFF]     : 0u;
        unsigned hp2 = (z <= DD - 3) ? g_hyst[wi + 2 * ZOFF] : 0u;
        unsigned dilm = hm2 | hm1 | h0;
        unsigned dil0 = hm1 | h0 | hp1;
        unsigned dilp = h0 | hp1 | hp2;
        my2 = (z ? dilm : 0xffffffffu) & dil0 &
              ((z < DD - 1) ? dilp : 0xffffffffu);
    }
    unsigned prev = __shfl_up_sync(0xffffffffu, my2, 1);
    if (lane == 0) prev = 0;
    unsigned sC = my2 & ~((my2 << 1) | (prev >> 31));
    int cnt = __popc(sC);
    int x = cnt;
#pragma unroll
    for (int o = 1; o < 32; o <<= 1) {
        int y = __shfl_up_sync(0xffffffffu, x, o);
        if (lane >= o) x += y;
    }
    if (lane < WPR) {
        g_mask2[wb + lane] = my2;
        g_pref[wb + lane] = (unsigned char)(x - cnt);
    }
    int nruns = __shfl_sync(0xffffffffu, x, 31);
    int initSlots = (nruns + 31) & ~31;
    for (int o = lane; o < initSlots; o += 32) {
        int ri = rbase + o;
        g_parent[ri] = ri;
        g_cnt[ri] = 0;
    }
}

// K5c (thread/word): flatten run starts + per-word-piece length at root
__global__ void k5c_flatten_count() {
    int wi = blockIdx.x * blockDim.x + threadIdx.x;
    if (wi >= NW) return;
    unsigned cur = g_mask2[wi];
    if (!cur) return;
    int row = wi / WPR, wd = wi - row * WPR;
    unsigned prevC = wd ? g_mask2[wi - 1] : 0;
    unsigned sC = cur & ~((cur << 1) | (prevC >> 31));
    int pC = g_pref[wi];
    int rbase = row * SLOTS;
    unsigned m = cur;
    while (m) {
        int b = __ffs(m) - 1;
        unsigned x = m >> b;
        int len = (x == 0xffffffffu) ? 32 : (__ffs(~x) - 1);
        unsigned seg = ((len == 32) ? 0xffffffffu : ((1u << len) - 1u)) << b;
        int ri = rbase + pC + __popc(sC & lemask(b)) - 1;
        int r = findRoot(g_parent, ri);
        if (((sC >> b) & 1) && r != ri) g_parent[ri] = r;
        atomicAdd(&g_cnt[r], len);
        m &= ~seg;
    }
}

// K6 (thread/word): keep mask per word, float4 stores
__global__ void k6_final(float* __restrict__ out) {
    int wi = blockIdx.x * blockDim.x + threadIdx.x;
    if (wi >= NW) return;
    unsigned cur = g_mask2[wi];
    unsigned keep = 0;
    if (cur) {
        int row = wi / WPR, wd = wi - row * WPR;
        unsigned prevC = wd ? g_mask2[wi - 1] : 0;
        unsigned sC = cur & ~((cur << 1) | (prevC >> 31));
        int pC = g_pref[wi];
        int rbase = row * SLOTS;
        unsigned m = cur;
        while (m) {
            int b = __ffs(m) - 1;
            unsigned x = m >> b;
            int len = (x == 0xffffffffu) ? 32 : (__ffs(~x) - 1);
            unsigned seg = ((len == 32) ? 0xffffffffu : ((1u << len) - 1u)) << b;
            int ri = rbase + pC + __popc(sC & lemask(b)) - 1;
            int r = findRoot(g_parent, ri);
            if (g_cnt[r] >= 20) keep |= seg;
            m &= ~seg;
        }
    }
    float4* out4 = reinterpret_cast<float4*>(out) + wi * 8;
#pragma unroll
    for (int k = 0; k < 8; k++) {
        out4[k] = make_float4(
            ((keep >> (4 * k + 0)) & 1) ? 1.0f : 0.0f,
            ((keep >> (4 * k + 1)) & 1) ? 1.0f : 0.0f,
            ((keep >> (4 * k + 2)) & 1) ? 1.0f : 0.0f,
            ((keep >> (4 * k + 3)) & 1) ? 1.0f : 0.0f);
    }
}

extern "C" void kernel_launch(void* const* d_in, const int* in_sizes, int n_in,
                              void* d_out, int out_size) {
    const float* in = (const float*)d_in[0];
    float* out = (float*)d_out;

    const int TPB = 256;
    const int GRID_ROW = (ROWS * 32) / TPB;     // 6144 (warp per row)
    const int GRID_W   = (NW + TPB - 1) / TPB;  // 2304 (thread per word)

    k1_threshold<<<GRID_ROW, TPB>>>(in);
    k2_merge<false><<<GRID_W, TPB>>>();
    k3_strong<<<GRID_W, TPB>>>();
    k4_hyst<<<GRID_W, TPB>>>();
    k5a_close<<<GRID_ROW, TPB>>>();
    k2_merge<true><<<GRID_W, TPB>>>();
    k5c_flatten_count<<<GRID_W, TPB>>>();
    k6_final<<<GRID_W, TPB>>>(out);
}